// round 1
// baseline (speedup 1.0000x reference)
#include <cuda_runtime.h>

#define BATCH 4096
#define NREL  128
#define EMB   256
#define KDIM  512   // 2*EMB

#define BM  32
#define BN  128
#define BKT 16

// Precomputed per-relation weights, stored k-major [k][r] for coalesced loads.
__device__ __align__(16) float g_w2[KDIM * NREL];
__device__ __align__(16) float g_w1[KDIM * NREL];
__device__ __align__(16) float g_const[NREL];

// One block per relation: compute w2 = -0.5/sigma^2, w1 = mu/sigma^2, and
// const_r = sum_k(-0.5 mu^2/sigma^2 - log sigma - LOG_SQRT_2PI) + prior*2D.
__global__ void prep_kernel(const float* __restrict__ mus,
                            const float* __restrict__ sigmas,
                            const float* __restrict__ priors) {
    const int r = blockIdx.x;
    const int k = threadIdx.x;   // 0..511

    const float s   = sigmas[r * KDIM + k];
    const float mu  = mus[r * KDIM + k];
    const float inv2 = 1.0f / (s * s);

    g_w2[k * NREL + r] = -0.5f * inv2;
    g_w1[k * NREL + r] = mu * inv2;

    float part = -0.5f * mu * mu * inv2 - logf(s) - 0.9189385332046727f;

    __shared__ float red[16];
    #pragma unroll
    for (int off = 16; off > 0; off >>= 1)
        part += __shfl_down_sync(0xffffffffu, part, off);
    if ((k & 31) == 0) red[k >> 5] = part;
    __syncthreads();
    if (k < 16) {
        float v = red[k];
        #pragma unroll
        for (int off = 8; off > 0; off >>= 1)
            v += __shfl_down_sync(0x0000ffffu, v, off);
        if (k == 0) g_const[r] = v + priors[r] * (float)KDIM;
    }
}

// Tiled contraction: out[b][r] = sum_k x*(w2*x + w1) + const[r]
// x[b][k] = concat(sbjs, objs) along k.
__global__ __launch_bounds__(256, 2)
void nb_main(const float* __restrict__ sbjs,
             const float* __restrict__ objs,
             float* __restrict__ out) {
    __shared__ __align__(16) float  Xs [BKT][BM];
    __shared__ __align__(16) float4 Ws2[BKT][BN / 4];
    __shared__ __align__(16) float4 Ws1[BKT][BN / 4];

    const int tid  = threadIdx.x;
    const int mt   = tid >> 5;    // 0..7  -> m group (4 rows each)
    const int nt   = tid & 31;    // 0..31 -> n group (4 cols each)
    const int brow = blockIdx.x * BM;

    float acc[4][4];
    #pragma unroll
    for (int i = 0; i < 4; i++)
        #pragma unroll
        for (int j = 0; j < 4; j++) acc[i][j] = 0.0f;

    // X-tile load mapping (threads 0..127): 32 rows x 4 float4 per row
    const int xrow = tid >> 2;         // 0..31
    const int xkq  = (tid & 3) * 4;    // 0,4,8,12

    for (int kt = 0; kt < KDIM; kt += BKT) {
        // ---- load X tile (transpose into Xs[k][m]) ----
        if (tid < 128) {
            const int b  = brow + xrow;
            const int kg = kt + xkq;
            const float* base = (kg < EMB) ? (sbjs + (size_t)b * EMB + kg)
                                           : (objs + (size_t)b * EMB + (kg - EMB));
            const float4 v = *reinterpret_cast<const float4*>(base);
            Xs[xkq + 0][xrow] = v.x;
            Xs[xkq + 1][xrow] = v.y;
            Xs[xkq + 2][xrow] = v.z;
            Xs[xkq + 3][xrow] = v.w;
        }
        // ---- load W tiles (already [k][r] in global, straight copy) ----
        #pragma unroll
        for (int i = 0; i < 2; i++) {
            const int idx = tid + i * 256;     // 0..511 float4 slots
            const int kk  = idx >> 5;          // 0..15
            const int c   = idx & 31;          // 0..31
            Ws2[kk][c] = *reinterpret_cast<const float4*>(&g_w2[(kt + kk) * NREL + c * 4]);
            Ws1[kk][c] = *reinterpret_cast<const float4*>(&g_w1[(kt + kk) * NREL + c * 4]);
        }
        __syncthreads();

        // ---- compute ----
        #pragma unroll
        for (int k = 0; k < BKT; k++) {
            const float4 xv  = *reinterpret_cast<const float4*>(&Xs[k][mt * 4]);
            const float4 w2v = Ws2[k][nt];
            const float4 w1v = Ws1[k][nt];
            const float xr[4] = {xv.x, xv.y, xv.z, xv.w};
            const float w2r[4] = {w2v.x, w2v.y, w2v.z, w2v.w};
            const float w1r[4] = {w1v.x, w1v.y, w1v.z, w1v.w};
            #pragma unroll
            for (int i = 0; i < 4; i++) {
                const float x = xr[i];
                #pragma unroll
                for (int j = 0; j < 4; j++) {
                    const float t = fmaf(w2r[j], x, w1r[j]);
                    acc[i][j] = fmaf(x, t, acc[i][j]);
                }
            }
        }
        __syncthreads();
    }

    // ---- epilogue ----
    const float4 cst = *reinterpret_cast<const float4*>(&g_const[nt * 4]);
    #pragma unroll
    for (int i = 0; i < 4; i++) {
        const int b = brow + mt * 4 + i;
        float4 o;
        o.x = acc[i][0] + cst.x;
        o.y = acc[i][1] + cst.y;
        o.z = acc[i][2] + cst.z;
        o.w = acc[i][3] + cst.w;
        *reinterpret_cast<float4*>(&out[(size_t)b * NREL + nt * 4]) = o;
    }
}

extern "C" void kernel_launch(void* const* d_in, const int* in_sizes, int n_in,
                              void* d_out, int out_size) {
    const float* sbjs   = (const float*)d_in[0];
    const float* objs   = (const float*)d_in[1];
    const float* mus    = (const float*)d_in[2];
    const float* sigmas = (const float*)d_in[3];
    const float* priors = (const float*)d_in[4];
    float* out = (float*)d_out;

    prep_kernel<<<NREL, KDIM>>>(mus, sigmas, priors);
    nb_main<<<BATCH / BM, 256>>>(sbjs, objs, out);
    (void)in_sizes; (void)n_in; (void)out_size;
}

// round 3
// speedup vs baseline: 2.3922x; 2.3922x over previous
#include <cuda_runtime.h>
#include <cuda_bf16.h>
#include <cstdint>

#define BATCH 4096
#define NREL  128
#define EMB   256
#define KDIM  512
#define KTOT  1024    // [x^2 ; x]
#define NCHUNK 16     // KTOT / 64
#define MT    32      // M tile per CTA -> 128 CTAs

// ---------------- device globals ----------------
__device__ __align__(16) __nv_bfloat16 g_B[NREL * KTOT];   // [r][k'] : w2 (k<512) then w1
__device__ __align__(16) float g_const[NREL];

__device__ __forceinline__ uint32_t smem_u32(const void* p) {
    uint32_t a;
    asm("{ .reg .u64 t; cvta.to.shared.u64 t, %1; cvt.u32.u64 %0, t; }" : "=r"(a) : "l"(p));
    return a;
}

__device__ __forceinline__ void ldsm_x4(uint32_t& r0, uint32_t& r1, uint32_t& r2, uint32_t& r3,
                                        uint32_t addr) {
    asm volatile("ldmatrix.sync.aligned.m8n8.x4.shared.b16 {%0,%1,%2,%3}, [%4];"
                 : "=r"(r0), "=r"(r1), "=r"(r2), "=r"(r3) : "r"(addr));
}

__device__ __forceinline__ void mma16816(float* d, const uint32_t* a, uint32_t b0, uint32_t b1) {
    asm volatile(
        "mma.sync.aligned.m16n8k16.row.col.f32.bf16.bf16.f32 "
        "{%0,%1,%2,%3}, {%4,%5,%6,%7}, {%8,%9}, {%0,%1,%2,%3};"
        : "+f"(d[0]), "+f"(d[1]), "+f"(d[2]), "+f"(d[3])
        : "r"(a[0]), "r"(a[1]), "r"(a[2]), "r"(a[3]), "r"(b0), "r"(b1));
}

// ---------------- prep: B = [w2 ; w1] bf16, const per relation ----------------
__global__ void prep_kernel(const float* __restrict__ mus,
                            const float* __restrict__ sigmas,
                            const float* __restrict__ priors) {
    const int r = blockIdx.x;
    const int k = threadIdx.x;   // 0..511

    const float s    = sigmas[r * KDIM + k];
    const float mu   = mus[r * KDIM + k];
    const float inv2 = 1.0f / (s * s);

    g_B[r * KTOT + k]        = __float2bfloat16(-0.5f * inv2);   // pairs with x^2
    g_B[r * KTOT + KDIM + k] = __float2bfloat16(mu * inv2);      // pairs with x

    float part = -0.5f * mu * mu * inv2 - logf(s) - 0.9189385332046727f;

    __shared__ float red[16];
    #pragma unroll
    for (int off = 16; off > 0; off >>= 1)
        part += __shfl_down_sync(0xffffffffu, part, off);
    if ((k & 31) == 0) red[k >> 5] = part;
    __syncthreads();
    if (k < 16) {
        float v = red[k];
        #pragma unroll
        for (int off = 8; off > 0; off >>= 1)
            v += __shfl_down_sync(0x0000ffffu, v, off);
        if (k == 0) g_const[r] = v + priors[r] * (float)KDIM;
    }
}

// ---------------- main: mma.sync bf16 GEMM ----------------
// A tile: 32 rows x 64 bf16 (128 B/row), B tile: 128 rows x 64 bf16.
// Swizzle: col ^= (row & 7) << 4 within the 128-byte row.
__global__ __launch_bounds__(256)
void nb_mma(const float* __restrict__ sbjs,
            const float* __restrict__ objs,
            float* __restrict__ out) {
    __shared__ __align__(16) char sA[2][MT * 128];      // 4 KB / stage
    __shared__ __align__(16) char sB[2][NREL * 128];    // 16 KB / stage

    const int tid  = threadIdx.x;
    const int lane = tid & 31;
    const int wid  = tid >> 5;
    const int brow = blockIdx.x * MT;

    const uint32_t aBase[2] = { smem_u32(sA[0]), smem_u32(sA[1]) };
    const uint32_t bBase[2] = { smem_u32(sB[0]), smem_u32(sB[1]) };

    // ---- loader mappings ----
    const int arow = tid >> 3;              // 0..31
    const int aoct = tid & 7;               // k-offset = aoct*8 floats
    const uint32_t aStsOff = (uint32_t)(arow * 128 + ((aoct * 16) ^ ((arow & 7) << 4)));

    const int brw  = tid >> 1;              // 0..127 relation row
    const int bhlf = tid & 1;               // 0/1 -> 64-byte half of the row
    uint32_t bStsOff[4];
    #pragma unroll
    for (int j = 0; j < 4; j++)
        bStsOff[j] = (uint32_t)(brw * 128 + (((bhlf * 64 + j * 16)) ^ ((brw & 7) << 4)));

    // ---- compute mappings ----
    const int wm = wid >> 2;                // 0..1 -> m offset 16
    const int wn = wid & 3;                 // 0..3 -> n offset 32
    const int mrow = wm * 16 + (lane & 15);
    const uint32_t aLdRow = (uint32_t)(mrow * 128);
    const uint32_t aLdXor = (uint32_t)(((mrow & 7) << 4));
    const uint32_t aLdBlk = (uint32_t)((lane >> 4) * 16);

    const int nrow0 = wn * 32 + ((lane >> 4) * 8) + (lane & 7);   // first x4 (n 0..15)
    const int nrow1 = nrow0 + 16;                                 // second x4 (n 16..31)
    const uint32_t bLdBlk = (uint32_t)(((lane >> 3) & 1) * 16);
    const uint32_t bLdRow0 = (uint32_t)(nrow0 * 128), bLdXor0 = (uint32_t)((nrow0 & 7) << 4);
    const uint32_t bLdRow1 = (uint32_t)(nrow1 * 128), bLdXor1 = (uint32_t)((nrow1 & 7) << 4);

    float acc[4][4];
    #pragma unroll
    for (int i = 0; i < 4; i++)
        #pragma unroll
        for (int j = 0; j < 4; j++) acc[i][j] = 0.0f;

    // ---- chunk 0 load ----
    {
        const float* src = sbjs + (size_t)(brow + arow) * EMB + aoct * 8;
        float4 v0 = reinterpret_cast<const float4*>(src)[0];
        float4 v1 = reinterpret_cast<const float4*>(src)[1];
        v0.x *= v0.x; v0.y *= v0.y; v0.z *= v0.z; v0.w *= v0.w;
        v1.x *= v1.x; v1.y *= v1.y; v1.z *= v1.z; v1.w *= v1.w;
        __nv_bfloat162 h0 = __floats2bfloat162_rn(v0.x, v0.y);
        __nv_bfloat162 h1 = __floats2bfloat162_rn(v0.z, v0.w);
        __nv_bfloat162 h2 = __floats2bfloat162_rn(v1.x, v1.y);
        __nv_bfloat162 h3 = __floats2bfloat162_rn(v1.z, v1.w);
        uint4 u;
        u.x = *reinterpret_cast<uint32_t*>(&h0);
        u.y = *reinterpret_cast<uint32_t*>(&h1);
        u.z = *reinterpret_cast<uint32_t*>(&h2);
        u.w = *reinterpret_cast<uint32_t*>(&h3);
        *reinterpret_cast<uint4*>(sA[0] + aStsOff) = u;

        const uint4* pb = reinterpret_cast<const uint4*>(g_B + (size_t)brw * KTOT + bhlf * 32);
        #pragma unroll
        for (int j = 0; j < 4; j++)
            *reinterpret_cast<uint4*>(sB[0] + bStsOff[j]) = pb[j];
    }
    __syncthreads();

    for (int c = 0; c < NCHUNK; c++) {
        const int s = c & 1;

        // ---- prefetch chunk c+1 (global -> regs) ----
        float4 pv0, pv1; uint4 pb[4];
        const bool have_next = (c + 1 < NCHUNK);
        if (have_next) {
            const int cn = c + 1;
            const int ck = cn & 7;
            const float* src = (ck < 4)
                ? sbjs + (size_t)(brow + arow) * EMB + ck * 64 + aoct * 8
                : objs + (size_t)(brow + arow) * EMB + (ck - 4) * 64 + aoct * 8;
            pv0 = reinterpret_cast<const float4*>(src)[0];
            pv1 = reinterpret_cast<const float4*>(src)[1];
            const uint4* pbs = reinterpret_cast<const uint4*>(
                g_B + (size_t)brw * KTOT + cn * 64 + bhlf * 32);
            #pragma unroll
            for (int j = 0; j < 4; j++) pb[j] = pbs[j];
        }

        // ---- compute chunk c: 4 k-steps ----
        #pragma unroll
        for (int ks = 0; ks < 4; ks++) {
            const uint32_t kcol = (uint32_t)(ks * 32);
            uint32_t a[4];
            ldsm_x4(a[0], a[1], a[2], a[3],
                    aBase[s] + aLdRow + ((kcol + aLdBlk) ^ aLdXor));
            uint32_t b[8];
            ldsm_x4(b[0], b[1], b[2], b[3],
                    bBase[s] + bLdRow0 + ((kcol + bLdBlk) ^ bLdXor0));
            ldsm_x4(b[4], b[5], b[6], b[7],
                    bBase[s] + bLdRow1 + ((kcol + bLdBlk) ^ bLdXor1));
            #pragma unroll
            for (int nf = 0; nf < 4; nf++)
                mma16816(acc[nf], a, b[nf * 2], b[nf * 2 + 1]);
        }

        // ---- convert + STS prefetched chunk into the other stage ----
        if (have_next) {
            if ((c + 1) < 8) {
                pv0.x *= pv0.x; pv0.y *= pv0.y; pv0.z *= pv0.z; pv0.w *= pv0.w;
                pv1.x *= pv1.x; pv1.y *= pv1.y; pv1.z *= pv1.z; pv1.w *= pv1.w;
            }
            __nv_bfloat162 h0 = __floats2bfloat162_rn(pv0.x, pv0.y);
            __nv_bfloat162 h1 = __floats2bfloat162_rn(pv0.z, pv0.w);
            __nv_bfloat162 h2 = __floats2bfloat162_rn(pv1.x, pv1.y);
            __nv_bfloat162 h3 = __floats2bfloat162_rn(pv1.z, pv1.w);
            uint4 u;
            u.x = *reinterpret_cast<uint32_t*>(&h0);
            u.y = *reinterpret_cast<uint32_t*>(&h1);
            u.z = *reinterpret_cast<uint32_t*>(&h2);
            u.w = *reinterpret_cast<uint32_t*>(&h3);
            *reinterpret_cast<uint4*>(sA[s ^ 1] + aStsOff) = u;
            #pragma unroll
            for (int j = 0; j < 4; j++)
                *reinterpret_cast<uint4*>(sB[s ^ 1] + bStsOff[j]) = pb[j];
        }
        __syncthreads();
    }

    // ---- epilogue: accum regs + const -> global ----
    #pragma unroll
    for (int nf = 0; nf < 4; nf++) {
        const int n0 = wn * 32 + nf * 8 + (lane & 3) * 2;
        const float c0 = g_const[n0], c1 = g_const[n0 + 1];
        const int r0 = brow + wm * 16 + (lane >> 2);
        float2 o0, o1;
        o0.x = acc[nf][0] + c0; o0.y = acc[nf][1] + c1;
        o1.x = acc[nf][2] + c0; o1.y = acc[nf][3] + c1;
        *reinterpret_cast<float2*>(&out[(size_t)r0 * NREL + n0])       = o0;
        *reinterpret_cast<float2*>(&out[(size_t)(r0 + 8) * NREL + n0]) = o1;
    }
}

extern "C" void kernel_launch(void* const* d_in, const int* in_sizes, int n_in,
                              void* d_out, int out_size) {
    const float* sbjs   = (const float*)d_in[0];
    const float* objs   = (const float*)d_in[1];
    const float* mus    = (const float*)d_in[2];
    const float* sigmas = (const float*)d_in[3];
    const float* priors = (const float*)d_in[4];
    float* out = (float*)d_out;

    prep_kernel<<<NREL, KDIM>>>(mus, sigmas, priors);
    nb_mma<<<BATCH / MT, 256>>>(sbjs, objs, out);
    (void)in_sizes; (void)n_in; (void)out_size;
}